// round 10
// baseline (speedup 1.0000x reference)
#include <cuda_runtime.h>
#include <cuda_bf16.h>
#include <math.h>
#include <stdint.h>

#define Bb 16
#define Ls 2048
#define Dd 256
#define Nn 32
#define Vv 1024
#define NLAY 4
#define Cn 16
#define Tc 128
#define Mrows (Bb*Ls)
#define DN (Dd*Nn)

__device__ __align__(16) float g_x[(size_t)Mrows*Dd];
__device__ __align__(16) float g_u[(size_t)Mrows*Dd];
__device__ __align__(16) float g_z[(size_t)Mrows*2*Dd];
__device__ __align__(16) __nv_bfloat16 g_ah[(size_t)Mrows*Dd];
__device__ __align__(16) __nv_bfloat16 g_al[(size_t)Mrows*Dd];
__device__ __align__(16) __nv_bfloat16 g_bh[(size_t)Mrows*4*Dd];
__device__ __align__(16) __nv_bfloat16 g_bl[(size_t)Mrows*4*Dd];
#define WT_TOTAL (8*512*256 + 4*1024*256 + 4*256*1024 + 1024*256)
__device__ __align__(16) __nv_bfloat16 g_wth[WT_TOTAL];
__device__ __align__(16) __nv_bfloat16 g_wtl[WT_TOTAL];
__device__ __align__(16) float2 g_E[(size_t)Bb*Dd*Cn*Nn];
__device__ __align__(16) float2 g_carry[(size_t)Bb*Dd*Cn*Nn];
__device__ __align__(16) float g_P[6*DN];

// ---------------- PTX helpers (plain sm_103-safe) ----------------
__device__ __forceinline__ uint32_t smem_u32(const void* p) {
    uint32_t a;
    asm("{ .reg .u64 t; cvta.to.shared.u64 t, %1; cvt.u32.u64 %0, t; }" : "=r"(a) : "l"(p));
    return a;
}
#define CP16(d,s)   asm volatile("cp.async.cg.shared.global [%0], [%1], 16;" :: "r"(d), "l"(s))
#define CP_COMMIT() asm volatile("cp.async.commit_group;" ::: "memory")
template<int NG> __device__ __forceinline__ void cp_wait() {
    asm volatile("cp.async.wait_group %0;" :: "n"(NG) : "memory");
}
__device__ __forceinline__ void ldm4(uint32_t* r, uint32_t a) {
    asm volatile("ldmatrix.sync.aligned.m8n8.x4.shared.b16 {%0,%1,%2,%3}, [%4];"
        : "=r"(r[0]), "=r"(r[1]), "=r"(r[2]), "=r"(r[3]) : "r"(a));
}
__device__ __forceinline__ void mma16816(float* d, const uint32_t* a, const uint32_t* b) {
    asm volatile("mma.sync.aligned.m16n8k16.row.col.f32.bf16.bf16.f32 "
        "{%0,%1,%2,%3}, {%4,%5,%6,%7}, {%8,%9}, {%0,%1,%2,%3};"
        : "+f"(d[0]), "+f"(d[1]), "+f"(d[2]), "+f"(d[3])
        : "r"(a[0]), "r"(a[1]), "r"(a[2]), "r"(a[3]), "r"(b[0]), "r"(b[1]));
}

__device__ __forceinline__ float gelu_tanh(float y) {
    float t = tanhf(0.7978845608028654f * fmaf(0.044715f * y, y * y, y));
    return 0.5f * y * (1.f + t);
}
__device__ __forceinline__ void split_store4(float4 v, __nv_bfloat16* ph, __nv_bfloat16* pl) {
    __nv_bfloat162 h01 = __floats2bfloat162_rn(v.x, v.y);
    __nv_bfloat162 h23 = __floats2bfloat162_rn(v.z, v.w);
    __nv_bfloat162 l01 = __floats2bfloat162_rn(v.x - __low2float(h01), v.y - __high2float(h01));
    __nv_bfloat162 l23 = __floats2bfloat162_rn(v.z - __low2float(h23), v.w - __high2float(h23));
    *reinterpret_cast<__nv_bfloat162*>(ph)     = h01;
    *reinterpret_cast<__nv_bfloat162*>(ph + 2) = h23;
    *reinterpret_cast<__nv_bfloat162*>(pl)     = l01;
    *reinterpret_cast<__nv_bfloat162*>(pl + 2) = l23;
}

// ---------------- elementwise / LN / params ----------------
__global__ void __launch_bounds__(256) embed_k(const int* __restrict__ batch,
                                               const float* __restrict__ emb) {
    int i = blockIdx.x * 256 + threadIdx.x;
    int row = i >> 6, c4 = i & 63;
    int tok = batch[row];
    reinterpret_cast<float4*>(g_x)[i] =
        reinterpret_cast<const float4*>(emb)[(size_t)tok * 64 + c4];
}

__global__ void __launch_bounds__(256) s4_params_k(const float* __restrict__ log_dt,
                                                   const float* __restrict__ Alogre,
                                                   const float* __restrict__ Aim,
                                                   const float* __restrict__ Cre,
                                                   const float* __restrict__ Cim) {
    int t = blockIdx.x * 256 + threadIdx.x;
    int d = t >> 5;
    float dt = expf(log_dt[d]);
    float are = -expf(Alogre[t]);
    float aim = Aim[t];
    float ar = dt * are, ai = dt * aim;
    float sn, cs;
    float er = expf(ar);
    sincosf(ai, &sn, &cs);
    float wr = er * cs, wi = er * sn;
    float eT = expf((float)Tc * ar);
    sincosf((float)Tc * ai, &sn, &cs);
    float nr = wr - 1.f, ni = wi;
    float inv = 1.f / (are * are + aim * aim);
    float qr = (nr * are + ni * aim) * inv;
    float qi = (ni * are - nr * aim) * inv;
    float crv = Cre[t], civ = Cim[t];
    g_P[0 * DN + t] = wr;
    g_P[1 * DN + t] = wi;
    g_P[2 * DN + t] = eT * cs;
    g_P[3 * DN + t] = eT * sn;
    g_P[4 * DN + t] = 2.f * (crv * qr - civ * qi);
    g_P[5 * DN + t] = 2.f * (crv * qi + civ * qr);
}

template <int BF>
__global__ void __launch_bounds__(256) layernorm_k(const float* __restrict__ x,
                                                   const float* __restrict__ w,
                                                   const float* __restrict__ b,
                                                   float* __restrict__ out) {
    int warp = threadIdx.x >> 5, lane = threadIdx.x & 31;
    int row = blockIdx.x * 8 + warp;
    const float4* xr = reinterpret_cast<const float4*>(x + (size_t)row * Dd);
    float4 v0 = xr[lane], v1 = xr[lane + 32];
    float s  = v0.x + v0.y + v0.z + v0.w + v1.x + v1.y + v1.z + v1.w;
    float ss = v0.x*v0.x + v0.y*v0.y + v0.z*v0.z + v0.w*v0.w
             + v1.x*v1.x + v1.y*v1.y + v1.z*v1.z + v1.w*v1.w;
    #pragma unroll
    for (int o = 16; o; o >>= 1) {
        s  += __shfl_xor_sync(0xffffffffu, s, o);
        ss += __shfl_xor_sync(0xffffffffu, ss, o);
    }
    float mu = s * (1.f / Dd);
    float var = ss * (1.f / Dd) - mu * mu;
    float rs = rsqrtf(var + 1e-5f);
    const float4* w4 = reinterpret_cast<const float4*>(w);
    const float4* b4 = reinterpret_cast<const float4*>(b);
    float4 wa = w4[lane], wb = w4[lane + 32];
    float4 ba = b4[lane], bb = b4[lane + 32];
    float4 o0, o1;
    o0.x=(v0.x-mu)*rs*wa.x+ba.x; o0.y=(v0.y-mu)*rs*wa.y+ba.y;
    o0.z=(v0.z-mu)*rs*wa.z+ba.z; o0.w=(v0.w-mu)*rs*wa.w+ba.w;
    o1.x=(v1.x-mu)*rs*wb.x+bb.x; o1.y=(v1.y-mu)*rs*wb.y+bb.y;
    o1.z=(v1.z-mu)*rs*wb.z+bb.z; o1.w=(v1.w-mu)*rs*wb.w+bb.w;
    if (BF) {
        size_t base = (size_t)row * Dd + 4 * lane;
        split_store4(o0, g_ah + base, g_al + base);
        split_store4(o1, g_ah + base + 128, g_al + base + 128);
    } else {
        float4* orow = reinterpret_cast<float4*>(out + (size_t)row * Dd);
        orow[lane] = o0; orow[lane + 32] = o1;
    }
}

// ---------------- weight transpose + split ----------------
__global__ void __launch_bounds__(256) wconv_k(const float* __restrict__ W, int K, int N,
                                               __nv_bfloat16* __restrict__ oh,
                                               __nv_bfloat16* __restrict__ ol) {
    __shared__ float t[32][33];
    int n0 = blockIdx.x * 32, k0 = blockIdx.y * 32;
    int tx = threadIdx.x & 31, ty = threadIdx.x >> 5;
    #pragma unroll
    for (int i = 0; i < 4; i++)
        t[ty + 8 * i][tx] = W[(size_t)(k0 + ty + 8 * i) * N + n0 + tx];
    __syncthreads();
    #pragma unroll
    for (int i = 0; i < 4; i++) {
        float v = t[tx][ty + 8 * i];
        __nv_bfloat16 h = __float2bfloat16(v);
        size_t o = (size_t)(n0 + ty + 8 * i) * K + k0 + tx;
        oh[o] = h;
        ol[o] = __float2bfloat16(v - __bfloat162float(h));
    }
}

// ---------------- scans ----------------
__global__ void __launch_bounds__(256) scan1_k() {
    int tid = threadIdx.x;
    int q = tid & 3, item = tid >> 2;
    int bx = blockIdx.x;
    int dt64 = bx & 3, c = (bx >> 2) & 15, b = bx >> 6;
    int d = dt64 * 64 + item;
    float wr[8], wi[8], sr[8], si[8];
    int pbase = d * Nn + q * 8;
    #pragma unroll
    for (int m = 0; m < 8; m++) {
        wr[m] = g_P[0 * DN + pbase + m];
        wi[m] = g_P[1 * DN + pbase + m];
        sr[m] = 0.f; si[m] = 0.f;
    }
    const float* up = g_u + ((size_t)(b * Ls + c * Tc) * Dd + d);
    #pragma unroll 4
    for (int t = 0; t < Tc; t++) {
        float uv = up[(size_t)t * Dd];
        #pragma unroll
        for (int m = 0; m < 8; m++) {
            float nsr = fmaf(wr[m], sr[m], fmaf(-wi[m], si[m], uv));
            float nsi = fmaf(wi[m], sr[m], wr[m] * si[m]);
            sr[m] = nsr; si[m] = nsi;
        }
    }
    float2* Ep = g_E + ((size_t)((b * Dd + d) * Cn + c) * Nn + q * 8);
    #pragma unroll
    for (int m = 0; m < 8; m++) Ep[m] = make_float2(sr[m], si[m]);
}

__global__ void __launch_bounds__(256) carry_k() {
    int tid = blockIdx.x * 256 + threadIdx.x;
    int n = tid & 31, d = (tid >> 5) & 255, b = tid >> 13;
    float wTr = g_P[2 * DN + d * Nn + n];
    float wTi = g_P[3 * DN + d * Nn + n];
    float cr = 0.f, ci = 0.f;
    size_t base = (size_t)(b * Dd + d) * Cn;
    #pragma unroll
    for (int c = 0; c < Cn; c++) {
        g_carry[(base + c) * Nn + n] = make_float2(cr, ci);
        float2 e = g_E[(base + c) * Nn + n];
        float ncr = fmaf(wTr, cr, fmaf(-wTi, ci, e.x));
        float nci = fmaf(wTi, cr, fmaf(wTr, ci, e.y));
        cr = ncr; ci = nci;
    }
}

__global__ void __launch_bounds__(256) scan3_k(const float* __restrict__ Dsk) {
    int tid = threadIdx.x;
    int q = tid & 3, item = tid >> 2;
    int bx = blockIdx.x;
    int dt64 = bx & 3, c = (bx >> 2) & 15, b = bx >> 6;
    int d = dt64 * 64 + item;
    float wr[8], wi[8], c2r[8], c2i[8], sr[8], si[8];
    int pbase = d * Nn + q * 8;
    const float2* cp = g_carry + ((size_t)((b * Dd + d) * Cn + c) * Nn + q * 8);
    #pragma unroll
    for (int m = 0; m < 8; m++) {
        wr[m]  = g_P[0 * DN + pbase + m];
        wi[m]  = g_P[1 * DN + pbase + m];
        c2r[m] = g_P[4 * DN + pbase + m];
        c2i[m] = g_P[5 * DN + pbase + m];
        float2 cc = cp[m];
        sr[m] = cc.x; si[m] = cc.y;
    }
    float dsk = Dsk[d];
    size_t base = (size_t)(b * Ls + c * Tc) * Dd + d;
    const float* up = g_u + base;
    #pragma unroll 2
    for (int t = 0; t < Tc; t++) {
        float uv = up[(size_t)t * Dd];
        float acc = 0.f;
        #pragma unroll
        for (int m = 0; m < 8; m++) {
            float nsr = fmaf(wr[m], sr[m], fmaf(-wi[m], si[m], uv));
            float nsi = fmaf(wi[m], sr[m], wr[m] * si[m]);
            sr[m] = nsr; si[m] = nsi;
            acc = fmaf(c2r[m], nsr, acc);
            acc = fmaf(-c2i[m], nsi, acc);
        }
        acc += __shfl_xor_sync(0xffffffffu, acc, 1);
        acc += __shfl_xor_sync(0xffffffffu, acc, 2);
        if (q == 0) {
            float gy = gelu_tanh(fmaf(uv, dsk, acc));
            __nv_bfloat16 h = __float2bfloat16(gy);
            size_t o = base + (size_t)t * Dd;
            g_ah[o] = h;
            g_al[o] = __float2bfloat16(gy - __bfloat162float(h));
        }
    }
}

// ---------------- split-bf16 HMMA GEMM, 128x256 CTA tile --------------------
// 8 warps (2m x 4n), 64x64 per warp, Kc=64, cp.async double buffer, SW128.
// EPI: 0 f32 store, 1 gelu->bf16 split, 2 f32 residual add
#define STG_BYTES 98304
#define GEMM_SMEM (2*STG_BYTES + 1024)

template <int ROWS>
__device__ __forceinline__ void load_tile(uint32_t sdst, const __nv_bfloat16* g, int ld) {
    int t = threadIdx.x;
    constexpr int PER = ROWS * 8 / 256;
    #pragma unroll
    for (int i = 0; i < PER; i++) {
        int idx = t * PER + i;
        int row = idx >> 3, c16 = idx & 7;
        uint32_t sw = (uint32_t)(row * 128) + (uint32_t)((c16 ^ (row & 7)) * 16);
        CP16(sdst + sw, g + (size_t)row * ld + c16 * 8);
    }
}

template <int EPI>
__global__ void __launch_bounds__(256, 1) gemm_k(
    const __nv_bfloat16* __restrict__ Ah, const __nv_bfloat16* __restrict__ Al,
    const __nv_bfloat16* __restrict__ Wh, const __nv_bfloat16* __restrict__ Wl,
    const float* __restrict__ bias,
    float* __restrict__ C, __nv_bfloat16* __restrict__ Chi, __nv_bfloat16* __restrict__ Clo,
    int N, int K)
{
    extern __shared__ char dsm[];
    uint32_t sb = smem_u32(dsm);
    uint32_t TB = (sb + 1023) & ~1023u;
    int tid = threadIdx.x, wid = tid >> 5, lane = tid & 31;
    int m0 = blockIdx.y * 128, n0 = blockIdx.x * 256;
    int NC = K >> 6;
    int wm = wid & 1;        // 2 m-warps: 64 rows each
    int wn = wid >> 1;       // 4 n-warps: 64 cols each

    float acc[4][8][4];
    #pragma unroll
    for (int i = 0; i < 4; i++)
        #pragma unroll
        for (int j = 0; j < 8; j++)
            #pragma unroll
            for (int k = 0; k < 4; k++) acc[i][j][k] = 0.f;

    const __nv_bfloat16* Ab = Ah + (size_t)m0 * K;
    const __nv_bfloat16* Lb = Al + (size_t)m0 * K;
    const __nv_bfloat16* Wb = Wh + (size_t)n0 * K;
    const __nv_bfloat16* Vb = Wl + (size_t)n0 * K;

    load_tile<128>(TB,         Ab, K);
    load_tile<128>(TB + 16384, Lb, K);
    load_tile<256>(TB + 32768, Wb, K);
    load_tile<256>(TB + 65536, Vb, K);
    CP_COMMIT();

    uint32_t arow = (uint32_t)(wm * 64 + (lane & 7) + ((lane >> 3) & 1) * 8);
    uint32_t akc  = (uint32_t)((lane >> 4) & 1);
    uint32_t brow0 = (uint32_t)(wn * 64 + (lane & 7) + ((lane >> 4) & 1) * 8);
    uint32_t bkc  = (uint32_t)((lane >> 3) & 1);

    for (int c = 0; c < NC; c++) {
        int s = c & 1;
        uint32_t stg = TB + (uint32_t)s * STG_BYTES;
        if (c + 1 < NC) {
            uint32_t pst = TB + (uint32_t)(s ^ 1) * STG_BYTES;
            int k1 = (c + 1) << 6;
            load_tile<128>(pst,         Ab + k1, K);
            load_tile<128>(pst + 16384, Lb + k1, K);
            load_tile<256>(pst + 32768, Wb + k1, K);
            load_tile<256>(pst + 65536, Vb + k1, K);
            CP_COMMIT();
            cp_wait<1>();
        } else {
            cp_wait<0>();
        }
        __syncthreads();

        uint32_t aAh = stg, aAl = stg + 16384, aBh = stg + 32768, aBl = stg + 65536;
        #pragma unroll
        for (int k16 = 0; k16 < 4; k16++) {
            uint32_t ah[4][4], al[4][4], bh[8][2], bl[8][2];
            #pragma unroll
            for (int mi = 0; mi < 4; mi++) {
                uint32_t ro = arow + mi * 16;
                uint32_t off = ro * 128 + (((k16 * 2 + akc) ^ (ro & 7)) << 4);
                ldm4(ah[mi], aAh + off);
                ldm4(al[mi], aAl + off);
            }
            #pragma unroll
            for (int p = 0; p < 4; p++) {
                uint32_t ro = brow0 + p * 16;
                uint32_t off = ro * 128 + (((k16 * 2 + bkc) ^ (ro & 7)) << 4);
                uint32_t t[4];
                ldm4(t, aBh + off);
                bh[p*2][0] = t[0]; bh[p*2][1] = t[1];
                bh[p*2+1][0] = t[2]; bh[p*2+1][1] = t[3];
                ldm4(t, aBl + off);
                bl[p*2][0] = t[0]; bl[p*2][1] = t[1];
                bl[p*2+1][0] = t[2]; bl[p*2+1][1] = t[3];
            }
            #pragma unroll
            for (int mi = 0; mi < 4; mi++)
                #pragma unroll
                for (int ni = 0; ni < 8; ni++) {
                    mma16816(acc[mi][ni], ah[mi], bh[ni]);
                    mma16816(acc[mi][ni], ah[mi], bl[ni]);
                    mma16816(acc[mi][ni], al[mi], bh[ni]);
                }
        }
        __syncthreads();
    }

    // stage accumulators through SMEM (pitch 260) for coalesced epilogue
    float* st = reinterpret_cast<float*>(dsm + (TB - sb));
    int rbase = wm * 64 + (lane >> 2);
    int cbase = wn * 64 + (lane & 3) * 2;
    #pragma unroll
    for (int mi = 0; mi < 4; mi++)
        #pragma unroll
        for (int ni = 0; ni < 8; ni++) {
            int r = rbase + mi * 16, cc = cbase + ni * 8;
            *reinterpret_cast<float2*>(st + r * 260 + cc) =
                make_float2(acc[mi][ni][0], acc[mi][ni][1]);
            *reinterpret_cast<float2*>(st + (r + 8) * 260 + cc) =
                make_float2(acc[mi][ni][2], acc[mi][ni][3]);
        }
    __syncthreads();

    float4 b40 = *reinterpret_cast<const float4*>(bias + n0 + lane * 8);
    float4 b41 = *reinterpret_cast<const float4*>(bias + n0 + lane * 8 + 4);
    for (int rr = wid; rr < 128; rr += 8) {
        const float* srow = st + rr * 260 + lane * 8;
        float v0 = srow[0] + b40.x, v1 = srow[1] + b40.y;
        float v2 = srow[2] + b40.z, v3 = srow[3] + b40.w;
        float v4 = srow[4] + b41.x, v5 = srow[5] + b41.y;
        float v6 = srow[6] + b41.z, v7 = srow[7] + b41.w;
        size_t o = (size_t)(m0 + rr) * N + n0 + lane * 8;
        if (EPI == 0) {
            *reinterpret_cast<float4*>(C + o)     = make_float4(v0, v1, v2, v3);
            *reinterpret_cast<float4*>(C + o + 4) = make_float4(v4, v5, v6, v7);
        } else if (EPI == 1) {
            float4 g0 = make_float4(gelu_tanh(v0), gelu_tanh(v1), gelu_tanh(v2), gelu_tanh(v3));
            float4 g1 = make_float4(gelu_tanh(v4), gelu_tanh(v5), gelu_tanh(v6), gelu_tanh(v7));
            split_store4(g0, Chi + o, Clo + o);
            split_store4(g1, Chi + o + 4, Clo + o + 4);
        } else {
            float4 x0 = *reinterpret_cast<const float4*>(C + o);
            float4 x1 = *reinterpret_cast<const float4*>(C + o + 4);
            x0.x += v0; x0.y += v1; x0.z += v2; x0.w += v3;
            x1.x += v4; x1.y += v5; x1.z += v6; x1.w += v7;
            *reinterpret_cast<float4*>(C + o)     = x0;
            *reinterpret_cast<float4*>(C + o + 4) = x1;
        }
    }
}

__global__ void __launch_bounds__(256) glu_k() {
    int i = blockIdx.x * 256 + threadIdx.x;
    int row = i >> 6, c4 = i & 63;
    const float4* z4 = reinterpret_cast<const float4*>(g_z);
    float4 a = z4[(size_t)row * 128 + c4];
    float4 g = z4[(size_t)row * 128 + 64 + c4];
    float4* x4 = reinterpret_cast<float4*>(g_x);
    float4 xo = x4[i];
    xo.x += a.x / (1.f + expf(-g.x));
    xo.y += a.y / (1.f + expf(-g.y));
    xo.z += a.z / (1.f + expf(-g.z));
    xo.w += a.w / (1.f + expf(-g.w));
    x4[i] = xo;
}

// ---------------- host ----------------
extern "C" void kernel_launch(void* const* d_in, const int* in_sizes, int n_in,
                              void* d_out, int out_size) {
    (void)in_sizes; (void)n_in; (void)out_size;
    const int*   batch     = (const int*)  d_in[0];
    const float* emb       = (const float*)d_in[1];
    const float* s4_ln_w   = (const float*)d_in[2];
    const float* s4_ln_b   = (const float*)d_in[3];
    const float* s4_log_dt = (const float*)d_in[4];
    const float* s4_Alogre = (const float*)d_in[5];
    const float* s4_Aim    = (const float*)d_in[6];
    const float* s4_Cre    = (const float*)d_in[7];
    const float* s4_Cim    = (const float*)d_in[8];
    const float* s4_Dsk    = (const float*)d_in[9];
    const float* s4_Wout   = (const float*)d_in[10];
    const float* s4_bout   = (const float*)d_in[11];
    const float* ff_ln_w   = (const float*)d_in[12];
    const float* ff_ln_b   = (const float*)d_in[13];
    const float* ff_W1     = (const float*)d_in[14];
    const float* ff_b1     = (const float*)d_in[15];
    const float* ff_W2     = (const float*)d_in[16];
    const float* ff_b2     = (const float*)d_in[17];
    const float* fin_ln_w  = (const float*)d_in[18];
    const float* fin_ln_b  = (const float*)d_in[19];
    const float* W_vocab   = (const float*)d_in[20];
    const float* b_vocab   = (const float*)d_in[21];

    float *px, *pu, *pz;
    __nv_bfloat16 *pah, *pal, *pbh, *pbl, *pwh, *pwl;
    cudaGetSymbolAddress((void**)&px,  g_x);
    cudaGetSymbolAddress((void**)&pu,  g_u);
    cudaGetSymbolAddress((void**)&pz,  g_z);
    cudaGetSymbolAddress((void**)&pah, g_ah);
    cudaGetSymbolAddress((void**)&pal, g_al);
    cudaGetSymbolAddress((void**)&pbh, g_bh);
    cudaGetSymbolAddress((void**)&pbl, g_bl);
    cudaGetSymbolAddress((void**)&pwh, g_wth);
    cudaGetSymbolAddress((void**)&pwl, g_wtl);

    cudaFuncSetAttribute(gemm_k<0>, cudaFuncAttributeMaxDynamicSharedMemorySize, GEMM_SMEM);
    cudaFuncSetAttribute(gemm_k<1>, cudaFuncAttributeMaxDynamicSharedMemorySize, GEMM_SMEM);
    cudaFuncSetAttribute(gemm_k<2>, cudaFuncAttributeMaxDynamicSharedMemorySize, GEMM_SMEM);

    const size_t OFF_WOUT = 0;
    const size_t OFF_FF1  = (size_t)8 * 512 * 256;
    const size_t OFF_FF2  = OFF_FF1 + (size_t)4 * 1024 * 256;
    const size_t OFF_VOC  = OFF_FF2 + (size_t)4 * 256 * 1024;

    const int ELT = Mrows * 64 / 256;
    const int LNB = Mrows / 8;
    const int SCB = Bb * Cn * (Dd / 64);
    const int CAB = Bb * Dd * Nn / 256;

    embed_k<<<ELT, 256>>>(batch, emb);

    for (int j = 0; j < 8; j++)
        wconv_k<<<dim3(16, 8), 256>>>(s4_Wout + (size_t)j*256*512, 256, 512,
                                      pwh + OFF_WOUT + (size_t)j*512*256,
                                      pwl + OFF_WOUT + (size_t)j*512*256);
    for (int l = 0; l < NLAY; l++)
        wconv_k<<<dim3(32, 8), 256>>>(ff_W1 + (size_t)l*256*1024, 256, 1024,
                                      pwh + OFF_FF1 + (size_t)l*1024*256,
                                      pwl + OFF_FF1 + (size_t)l*1024*256);
    for (int l = 0; l < NLAY; l++)
        wconv_k<<<dim3(8, 32), 256>>>(ff_W2 + (size_t)l*1024*256, 1024, 256,
                                      pwh + OFF_FF2 + (size_t)l*256*1024,
                                      pwl + OFF_FF2 + (size_t)l*256*1024);
    wconv_k<<<dim3(32, 8), 256>>>(W_vocab, 256, 1024, pwh + OFF_VOC, pwl + OFF_VOC);

    for (int l = 0; l < NLAY; l++) {
        for (int s = 0; s < 2; s++) {
            int j = 2 * l + s;
            s4_params_k<<<DN / 256, 256>>>(s4_log_dt + (size_t)j * Dd,
                                           s4_Alogre + (size_t)j * DN,
                                           s4_Aim    + (size_t)j * DN,
                                           s4_Cre    + (size_t)j * DN,
                                           s4_Cim    + (size_t)j * DN);
            layernorm_k<0><<<LNB, 256>>>(px, s4_ln_w + (size_t)j * Dd,
                                         s4_ln_b + (size_t)j * Dd, pu);
            scan1_k<<<SCB, 256>>>();
            carry_k<<<CAB, 256>>>();
            scan3_k<<<SCB, 256>>>(s4_Dsk + (size_t)j * Dd);
            gemm_k<0><<<dim3(2, Mrows/128), 256, GEMM_SMEM>>>(
                pah, pal, pwh + OFF_WOUT + (size_t)j*512*256, pwl + OFF_WOUT + (size_t)j*512*256,
                s4_bout + (size_t)j * 512, pz, nullptr, nullptr, 512, 256);
            glu_k<<<ELT, 256>>>();
        }
        layernorm_k<1><<<LNB, 256>>>(px, ff_ln_w + (size_t)l * Dd,
                                     ff_ln_b + (size_t)l * Dd, nullptr);
        gemm_k<1><<<dim3(4, Mrows/128), 256, GEMM_SMEM>>>(
            pah, pal, pwh + OFF_FF1 + (size_t)l*1024*256, pwl + OFF_FF1 + (size_t)l*1024*256,
            ff_b1 + (size_t)l * 1024, nullptr, pbh, pbl, 1024, 256);
        gemm_k<2><<<dim3(1, Mrows/128), 256, GEMM_SMEM>>>(
            pbh, pbl, pwh + OFF_FF2 + (size_t)l*256*1024, pwl + OFF_FF2 + (size_t)l*256*1024,
            ff_b2 + (size_t)l * 256, px, nullptr, nullptr, 256, 1024);
    }

    layernorm_k<1><<<LNB, 256>>>(px, fin_ln_w, fin_ln_b, nullptr);
    gemm_k<0><<<dim3(4, Mrows/128), 256, GEMM_SMEM>>>(
        pah, pal, pwh + OFF_VOC, pwl + OFF_VOC,
        b_vocab, (float*)d_out, nullptr, nullptr, 1024, 256);
}

// round 11
// speedup vs baseline: 1.1346x; 1.1346x over previous
#include <cuda_runtime.h>
#include <cuda_bf16.h>
#include <math.h>
#include <stdint.h>

#define Bb 16
#define Ls 2048
#define Dd 256
#define Nn 32
#define Vv 1024
#define NLAY 4
#define Cn 16
#define Tc 128
#define Mrows (Bb*Ls)
#define DN (Dd*Nn)

__device__ __align__(16) float g_x[(size_t)Mrows*Dd];
__device__ __align__(16) float g_u[(size_t)Mrows*Dd];
__device__ __align__(16) float g_z[(size_t)Mrows*2*Dd];
__device__ __align__(16) __nv_bfloat16 g_ah[(size_t)Mrows*Dd];
__device__ __align__(16) __nv_bfloat16 g_al[(size_t)Mrows*Dd];
__device__ __align__(16) __nv_bfloat16 g_bh[(size_t)Mrows*4*Dd];
__device__ __align__(16) __nv_bfloat16 g_bl[(size_t)Mrows*4*Dd];
#define WT_TOTAL (8*512*256 + 4*1024*256 + 4*256*1024 + 1024*256)
__device__ __align__(16) __nv_bfloat16 g_wth[WT_TOTAL];
__device__ __align__(16) __nv_bfloat16 g_wtl[WT_TOTAL];
__device__ __align__(16) float2 g_E[(size_t)Bb*Dd*Cn*Nn];
__device__ __align__(16) float2 g_carry[(size_t)Bb*Dd*Cn*Nn];
__device__ __align__(16) float g_P[6*DN];

// ---------------- PTX helpers (plain sm_103-safe) ----------------
__device__ __forceinline__ uint32_t smem_u32(const void* p) {
    uint32_t a;
    asm("{ .reg .u64 t; cvta.to.shared.u64 t, %1; cvt.u32.u64 %0, t; }" : "=r"(a) : "l"(p));
    return a;
}
#define CP16(d,s)   asm volatile("cp.async.cg.shared.global [%0], [%1], 16;" :: "r"(d), "l"(s))
#define CP_COMMIT() asm volatile("cp.async.commit_group;" ::: "memory")
template<int NG> __device__ __forceinline__ void cp_wait() {
    asm volatile("cp.async.wait_group %0;" :: "n"(NG) : "memory");
}
__device__ __forceinline__ void ldm4(uint32_t* r, uint32_t a) {
    asm volatile("ldmatrix.sync.aligned.m8n8.x4.shared.b16 {%0,%1,%2,%3}, [%4];"
        : "=r"(r[0]), "=r"(r[1]), "=r"(r[2]), "=r"(r[3]) : "r"(a));
}
__device__ __forceinline__ void mma16816(float* d, const uint32_t* a, const uint32_t* b) {
    asm volatile("mma.sync.aligned.m16n8k16.row.col.f32.bf16.bf16.f32 "
        "{%0,%1,%2,%3}, {%4,%5,%6,%7}, {%8,%9}, {%0,%1,%2,%3};"
        : "+f"(d[0]), "+f"(d[1]), "+f"(d[2]), "+f"(d[3])
        : "r"(a[0]), "r"(a[1]), "r"(a[2]), "r"(a[3]), "r"(b[0]), "r"(b[1]));
}

__device__ __forceinline__ float gelu_tanh(float y) {
    float t = tanhf(0.7978845608028654f * fmaf(0.044715f * y, y * y, y));
    return 0.5f * y * (1.f + t);
}
__device__ __forceinline__ void split_store4(float4 v, __nv_bfloat16* ph, __nv_bfloat16* pl) {
    __nv_bfloat162 h01 = __floats2bfloat162_rn(v.x, v.y);
    __nv_bfloat162 h23 = __floats2bfloat162_rn(v.z, v.w);
    __nv_bfloat162 l01 = __floats2bfloat162_rn(v.x - __low2float(h01), v.y - __high2float(h01));
    __nv_bfloat162 l23 = __floats2bfloat162_rn(v.z - __low2float(h23), v.w - __high2float(h23));
    *reinterpret_cast<__nv_bfloat162*>(ph)     = h01;
    *reinterpret_cast<__nv_bfloat162*>(ph + 2) = h23;
    *reinterpret_cast<__nv_bfloat162*>(pl)     = l01;
    *reinterpret_cast<__nv_bfloat162*>(pl + 2) = l23;
}

// ---------------- elementwise / LN / params ----------------
__global__ void __launch_bounds__(256) embed_k(const int* __restrict__ batch,
                                               const float* __restrict__ emb) {
    int i = blockIdx.x * 256 + threadIdx.x;
    int row = i >> 6, c4 = i & 63;
    int tok = batch[row];
    reinterpret_cast<float4*>(g_x)[i] =
        reinterpret_cast<const float4*>(emb)[(size_t)tok * 64 + c4];
}

__global__ void __launch_bounds__(256) s4_params_k(const float* __restrict__ log_dt,
                                                   const float* __restrict__ Alogre,
                                                   const float* __restrict__ Aim,
                                                   const float* __restrict__ Cre,
                                                   const float* __restrict__ Cim) {
    int t = blockIdx.x * 256 + threadIdx.x;
    int d = t >> 5;
    float dt = expf(log_dt[d]);
    float are = -expf(Alogre[t]);
    float aim = Aim[t];
    float ar = dt * are, ai = dt * aim;
    float sn, cs;
    float er = expf(ar);
    sincosf(ai, &sn, &cs);
    float wr = er * cs, wi = er * sn;
    float eT = expf((float)Tc * ar);
    sincosf((float)Tc * ai, &sn, &cs);
    float nr = wr - 1.f, ni = wi;
    float inv = 1.f / (are * are + aim * aim);
    float qr = (nr * are + ni * aim) * inv;
    float qi = (ni * are - nr * aim) * inv;
    float crv = Cre[t], civ = Cim[t];
    g_P[0 * DN + t] = wr;
    g_P[1 * DN + t] = wi;
    g_P[2 * DN + t] = eT * cs;
    g_P[3 * DN + t] = eT * sn;
    g_P[4 * DN + t] = 2.f * (crv * qr - civ * qi);
    g_P[5 * DN + t] = 2.f * (crv * qi + civ * qr);
}

template <int BF>
__global__ void __launch_bounds__(256) layernorm_k(const float* __restrict__ x,
                                                   const float* __restrict__ w,
                                                   const float* __restrict__ b,
                                                   float* __restrict__ out) {
    int warp = threadIdx.x >> 5, lane = threadIdx.x & 31;
    int row = blockIdx.x * 8 + warp;
    const float4* xr = reinterpret_cast<const float4*>(x + (size_t)row * Dd);
    float4 v0 = xr[lane], v1 = xr[lane + 32];
    float s  = v0.x + v0.y + v0.z + v0.w + v1.x + v1.y + v1.z + v1.w;
    float ss = v0.x*v0.x + v0.y*v0.y + v0.z*v0.z + v0.w*v0.w
             + v1.x*v1.x + v1.y*v1.y + v1.z*v1.z + v1.w*v1.w;
    #pragma unroll
    for (int o = 16; o; o >>= 1) {
        s  += __shfl_xor_sync(0xffffffffu, s, o);
        ss += __shfl_xor_sync(0xffffffffu, ss, o);
    }
    float mu = s * (1.f / Dd);
    float var = ss * (1.f / Dd) - mu * mu;
    float rs = rsqrtf(var + 1e-5f);
    const float4* w4 = reinterpret_cast<const float4*>(w);
    const float4* b4 = reinterpret_cast<const float4*>(b);
    float4 wa = w4[lane], wb = w4[lane + 32];
    float4 ba = b4[lane], bb = b4[lane + 32];
    float4 o0, o1;
    o0.x=(v0.x-mu)*rs*wa.x+ba.x; o0.y=(v0.y-mu)*rs*wa.y+ba.y;
    o0.z=(v0.z-mu)*rs*wa.z+ba.z; o0.w=(v0.w-mu)*rs*wa.w+ba.w;
    o1.x=(v1.x-mu)*rs*wb.x+bb.x; o1.y=(v1.y-mu)*rs*wb.y+bb.y;
    o1.z=(v1.z-mu)*rs*wb.z+bb.z; o1.w=(v1.w-mu)*rs*wb.w+bb.w;
    if (BF) {
        size_t base = (size_t)row * Dd + 4 * lane;
        split_store4(o0, g_ah + base, g_al + base);
        split_store4(o1, g_ah + base + 128, g_al + base + 128);
    } else {
        float4* orow = reinterpret_cast<float4*>(out + (size_t)row * Dd);
        orow[lane] = o0; orow[lane + 32] = o1;
    }
}

// ---------------- weight transpose + split ----------------
__global__ void __launch_bounds__(256) wconv_k(const float* __restrict__ W, int K, int N,
                                               __nv_bfloat16* __restrict__ oh,
                                               __nv_bfloat16* __restrict__ ol) {
    __shared__ float t[32][33];
    int n0 = blockIdx.x * 32, k0 = blockIdx.y * 32;
    int tx = threadIdx.x & 31, ty = threadIdx.x >> 5;
    #pragma unroll
    for (int i = 0; i < 4; i++)
        t[ty + 8 * i][tx] = W[(size_t)(k0 + ty + 8 * i) * N + n0 + tx];
    __syncthreads();
    #pragma unroll
    for (int i = 0; i < 4; i++) {
        float v = t[tx][ty + 8 * i];
        __nv_bfloat16 h = __float2bfloat16(v);
        size_t o = (size_t)(n0 + ty + 8 * i) * K + k0 + tx;
        oh[o] = h;
        ol[o] = __float2bfloat16(v - __bfloat162float(h));
    }
}

// ---------------- scans ----------------
__global__ void __launch_bounds__(256) scan1_k() {
    int tid = threadIdx.x;
    int q = tid & 3, item = tid >> 2;
    int bx = blockIdx.x;
    int dt64 = bx & 3, c = (bx >> 2) & 15, b = bx >> 6;
    int d = dt64 * 64 + item;
    float wr[8], wi[8], sr[8], si[8];
    int pbase = d * Nn + q * 8;
    #pragma unroll
    for (int m = 0; m < 8; m++) {
        wr[m] = g_P[0 * DN + pbase + m];
        wi[m] = g_P[1 * DN + pbase + m];
        sr[m] = 0.f; si[m] = 0.f;
    }
    const float* up = g_u + ((size_t)(b * Ls + c * Tc) * Dd + d);
    #pragma unroll 4
    for (int t = 0; t < Tc; t++) {
        float uv = up[(size_t)t * Dd];
        #pragma unroll
        for (int m = 0; m < 8; m++) {
            float nsr = fmaf(wr[m], sr[m], fmaf(-wi[m], si[m], uv));
            float nsi = fmaf(wi[m], sr[m], wr[m] * si[m]);
            sr[m] = nsr; si[m] = nsi;
        }
    }
    float2* Ep = g_E + ((size_t)((b * Dd + d) * Cn + c) * Nn + q * 8);
    #pragma unroll
    for (int m = 0; m < 8; m++) Ep[m] = make_float2(sr[m], si[m]);
}

__global__ void __launch_bounds__(256) carry_k() {
    int tid = blockIdx.x * 256 + threadIdx.x;
    int n = tid & 31, d = (tid >> 5) & 255, b = tid >> 13;
    float wTr = g_P[2 * DN + d * Nn + n];
    float wTi = g_P[3 * DN + d * Nn + n];
    float cr = 0.f, ci = 0.f;
    size_t base = (size_t)(b * Dd + d) * Cn;
    #pragma unroll
    for (int c = 0; c < Cn; c++) {
        g_carry[(base + c) * Nn + n] = make_float2(cr, ci);
        float2 e = g_E[(base + c) * Nn + n];
        float ncr = fmaf(wTr, cr, fmaf(-wTi, ci, e.x));
        float nci = fmaf(wTi, cr, fmaf(wTr, ci, e.y));
        cr = ncr; ci = nci;
    }
}

__global__ void __launch_bounds__(256) scan3_k(const float* __restrict__ Dsk) {
    int tid = threadIdx.x;
    int q = tid & 3, item = tid >> 2;
    int bx = blockIdx.x;
    int dt64 = bx & 3, c = (bx >> 2) & 15, b = bx >> 6;
    int d = dt64 * 64 + item;
    float wr[8], wi[8], c2r[8], c2i[8], sr[8], si[8];
    int pbase = d * Nn + q * 8;
    const float2* cp = g_carry + ((size_t)((b * Dd + d) * Cn + c) * Nn + q * 8);
    #pragma unroll
    for (int m = 0; m < 8; m++) {
        wr[m]  = g_P[0 * DN + pbase + m];
        wi[m]  = g_P[1 * DN + pbase + m];
        c2r[m] = g_P[4 * DN + pbase + m];
        c2i[m] = g_P[5 * DN + pbase + m];
        float2 cc = cp[m];
        sr[m] = cc.x; si[m] = cc.y;
    }
    float dsk = Dsk[d];
    size_t base = (size_t)(b * Ls + c * Tc) * Dd + d;
    const float* up = g_u + base;
    #pragma unroll 2
    for (int t = 0; t < Tc; t++) {
        float uv = up[(size_t)t * Dd];
        float acc = 0.f;
        #pragma unroll
        for (int m = 0; m < 8; m++) {
            float nsr = fmaf(wr[m], sr[m], fmaf(-wi[m], si[m], uv));
            float nsi = fmaf(wi[m], sr[m], wr[m] * si[m]);
            sr[m] = nsr; si[m] = nsi;
            acc = fmaf(c2r[m], nsr, acc);
            acc = fmaf(-c2i[m], nsi, acc);
        }
        acc += __shfl_xor_sync(0xffffffffu, acc, 1);
        acc += __shfl_xor_sync(0xffffffffu, acc, 2);
        if (q == 0) {
            float gy = gelu_tanh(fmaf(uv, dsk, acc));
            __nv_bfloat16 h = __float2bfloat16(gy);
            size_t o = base + (size_t)t * Dd;
            g_ah[o] = h;
            g_al[o] = __float2bfloat16(gy - __bfloat162float(h));
        }
    }
}

// ---------------- split-bf16 HMMA GEMM, 128x256 CTA, 512 thr ----------------
// 16 warps (2m x 8n), 64x32 per warp (R9's proven shape), Kc=64, double buffer.
// Direct register->gmem epilogue (no smem staging).
// EPI: 0 f32 store, 1 gelu->bf16 split, 2 f32 residual add
#define STG_BYTES 98304
#define GEMM_SMEM (2*STG_BYTES)

template <int ROWS>
__device__ __forceinline__ void load_tile(uint32_t sdst, const __nv_bfloat16* g, int ld) {
    int t = threadIdx.x;
    constexpr int PER = ROWS * 8 / 512;
    #pragma unroll
    for (int i = 0; i < PER; i++) {
        int idx = t * PER + i;
        int row = idx >> 3, c16 = idx & 7;
        uint32_t sw = (uint32_t)(row * 128) + (uint32_t)((c16 ^ (row & 7)) * 16);
        CP16(sdst + sw, g + (size_t)row * ld + c16 * 8);
    }
}

template <int EPI>
__global__ void __launch_bounds__(512, 1) gemm_k(
    const __nv_bfloat16* __restrict__ Ah, const __nv_bfloat16* __restrict__ Al,
    const __nv_bfloat16* __restrict__ Wh, const __nv_bfloat16* __restrict__ Wl,
    const float* __restrict__ bias,
    float* __restrict__ C, __nv_bfloat16* __restrict__ Chi, __nv_bfloat16* __restrict__ Clo,
    int N, int K)
{
    extern __shared__ char dsm[];
    uint32_t TB = smem_u32(dsm);
    int tid = threadIdx.x, wid = tid >> 5, lane = tid & 31;
    int m0 = blockIdx.y * 128, n0 = blockIdx.x * 256;
    int NC = K >> 6;
    int wm = wid & 1;        // 2 m-warps: 64 rows
    int wn = wid >> 1;       // 8 n-warps: 32 cols

    float acc[4][4][4];
    #pragma unroll
    for (int i = 0; i < 4; i++)
        #pragma unroll
        for (int j = 0; j < 4; j++)
            #pragma unroll
            for (int k = 0; k < 4; k++) acc[i][j][k] = 0.f;

    const __nv_bfloat16* Ab = Ah + (size_t)m0 * K;
    const __nv_bfloat16* Lb = Al + (size_t)m0 * K;
    const __nv_bfloat16* Wb = Wh + (size_t)n0 * K;
    const __nv_bfloat16* Vb = Wl + (size_t)n0 * K;

    load_tile<128>(TB,         Ab, K);
    load_tile<128>(TB + 16384, Lb, K);
    load_tile<256>(TB + 32768, Wb, K);
    load_tile<256>(TB + 65536, Vb, K);
    CP_COMMIT();

    uint32_t arow  = (uint32_t)(wm * 64 + (lane & 7) + ((lane >> 3) & 1) * 8);
    uint32_t akc   = (uint32_t)((lane >> 4) & 1);
    uint32_t brow0 = (uint32_t)(wn * 32 + (lane & 7) + ((lane >> 4) & 1) * 8);
    uint32_t bkc   = (uint32_t)((lane >> 3) & 1);

    for (int c = 0; c < NC; c++) {
        int s = c & 1;
        uint32_t stg = TB + (uint32_t)s * STG_BYTES;
        if (c + 1 < NC) {
            uint32_t pst = TB + (uint32_t)(s ^ 1) * STG_BYTES;
            int k1 = (c + 1) << 6;
            load_tile<128>(pst,         Ab + k1, K);
            load_tile<128>(pst + 16384, Lb + k1, K);
            load_tile<256>(pst + 32768, Wb + k1, K);
            load_tile<256>(pst + 65536, Vb + k1, K);
            CP_COMMIT();
            cp_wait<1>();
        } else {
            cp_wait<0>();
        }
        __syncthreads();

        uint32_t aAh = stg, aAl = stg + 16384, aBh = stg + 32768, aBl = stg + 65536;
        #pragma unroll
        for (int k16 = 0; k16 < 4; k16++) {
            uint32_t ah[4][4], al[4][4], bh[4][2], bl[4][2];
            #pragma unroll
            for (int mi = 0; mi < 4; mi++) {
                uint32_t ro = arow + mi * 16;
                uint32_t off = ro * 128 + (((k16 * 2 + akc) ^ (ro & 7)) << 4);
                ldm4(ah[mi], aAh + off);
                ldm4(al[mi], aAl + off);
            }
            #pragma unroll
            for (int p = 0; p < 2; p++) {
                uint32_t ro = brow0 + p * 16;
                uint32_t off = ro * 128 + (((k16 * 2 + bkc) ^ (ro & 7)) << 4);
                uint32_t t[4];
                ldm4(t, aBh + off);
                bh[p*2][0] = t[0]; bh[p*2][1] = t[1];
                bh[p*2+1][0] = t[2]; bh[p*2+1][1] = t[3];
                ldm4(t, aBl + off);
                bl[p*2][0] = t[0]; bl[p*2][1] = t[1];
                bl[p*2+1][0] = t[2]; bl[p*2+1][1] = t[3];
            }
            #pragma unroll
            for (int mi = 0; mi < 4; mi++)
                #pragma unroll
                for (int ni = 0; ni < 4; ni++) {
                    mma16816(acc[mi][ni], ah[mi], bh[ni]);
                    mma16816(acc[mi][ni], ah[mi], bl[ni]);
                    mma16816(acc[mi][ni], al[mi], bh[ni]);
                }
        }
        __syncthreads();
    }

    // direct register -> gmem epilogue (fragment layout: row = lane>>2 (+8),
    // col pair = (lane&3)*2 + ni*8 within the warp's 32 columns)
    int cA = n0 + wn * 32 + (lane & 3) * 2;
    float2 bv[4];
    #pragma unroll
    for (int ni = 0; ni < 4; ni++)
        bv[ni] = *reinterpret_cast<const float2*>(bias + cA + ni * 8);
    int r0 = m0 + wm * 64 + (lane >> 2);
    #pragma unroll
    for (int mi = 0; mi < 4; mi++) {
        #pragma unroll
        for (int half = 0; half < 2; half++) {
            int r = r0 + mi * 16 + half * 8;
            #pragma unroll
            for (int ni = 0; ni < 4; ni++) {
                float v0 = acc[mi][ni][half * 2]     + bv[ni].x;
                float v1 = acc[mi][ni][half * 2 + 1] + bv[ni].y;
                size_t o = (size_t)r * N + cA + ni * 8;
                if (EPI == 0) {
                    *reinterpret_cast<float2*>(C + o) = make_float2(v0, v1);
                } else if (EPI == 1) {
                    float gy0 = gelu_tanh(v0), gy1 = gelu_tanh(v1);
                    __nv_bfloat162 h = __floats2bfloat162_rn(gy0, gy1);
                    __nv_bfloat162 lo = __floats2bfloat162_rn(
                        gy0 - __low2float(h), gy1 - __high2float(h));
                    *reinterpret_cast<__nv_bfloat162*>(Chi + o) = h;
                    *reinterpret_cast<__nv_bfloat162*>(Clo + o) = lo;
                } else {
                    float2 x = *reinterpret_cast<const float2*>(C + o);
                    x.x += v0; x.y += v1;
                    *reinterpret_cast<float2*>(C + o) = x;
                }
            }
        }
    }
}

__global__ void __launch_bounds__(256) glu_k() {
    int i = blockIdx.x * 256 + threadIdx.x;
    int row = i >> 6, c4 = i & 63;
    const float4* z4 = reinterpret_cast<const float4*>(g_z);
    float4 a = z4[(size_t)row * 128 + c4];
    float4 g = z4[(size_t)row * 128 + 64 + c4];
    float4* x4 = reinterpret_cast<float4*>(g_x);
    float4 xo = x4[i];
    xo.x += a.x / (1.f + expf(-g.x));
    xo.y += a.y / (1.f + expf(-g.y));
    xo.z += a.z / (1.f + expf(-g.z));
    xo.w += a.w / (1.f + expf(-g.w));
    x4[i] = xo;
}

// ---------------- host ----------------
extern "C" void kernel_launch(void* const* d_in, const int* in_sizes, int n_in,
                              void* d_out, int out_size) {
    (void)in_sizes; (void)n_in; (void)out_size;
    const int*   batch     = (const int*)  d_in[0];
    const float* emb       = (const float*)d_in[1];
    const float* s4_ln_w   = (const float*)d_in[2];
    const float* s4_ln_b   = (const float*)d_in[3];
    const float* s4_log_dt = (const float*)d_in[4];
    const float* s4_Alogre = (const float*)d_in[5];
    const float* s4_Aim    = (const float*)d_in[6];
    const float* s4_Cre    = (const float*)d_in[7];
    const float* s4_Cim    = (const float*)d_in[8];
    const float* s4_Dsk    = (const float*)d_in[9];
    const float* s4_Wout   = (const float*)d_in[10];
    const float* s4_bout   = (const float*)d_in[11];
    const float* ff_ln_w   = (const float*)d_in[12];
    const float* ff_ln_b   = (const float*)d_in[13];
    const float* ff_W1     = (const float*)d_in[14];
    const float* ff_b1     = (const float*)d_in[15];
    const float* ff_W2     = (const float*)d_in[16];
    const float* ff_b2     = (const float*)d_in[17];
    const float* fin_ln_w  = (const float*)d_in[18];
    const float* fin_ln_b  = (const float*)d_in[19];
    const float* W_vocab   = (const float*)d_in[20];
    const float* b_vocab   = (const float*)d_in[21];

    float *px, *pu, *pz;
    __nv_bfloat16 *pah, *pal, *pbh, *pbl, *pwh, *pwl;
    cudaGetSymbolAddress((void**)&px,  g_x);
    cudaGetSymbolAddress((void**)&pu,  g_u);
    cudaGetSymbolAddress((void**)&pz,  g_z);
    cudaGetSymbolAddress((void**)&pah, g_ah);
    cudaGetSymbolAddress((void**)&pal, g_al);
    cudaGetSymbolAddress((void**)&pbh, g_bh);
    cudaGetSymbolAddress((void**)&pbl, g_bl);
    cudaGetSymbolAddress((void**)&pwh, g_wth);
    cudaGetSymbolAddress((void**)&pwl, g_wtl);

    cudaFuncSetAttribute(gemm_k<0>, cudaFuncAttributeMaxDynamicSharedMemorySize, GEMM_SMEM);
    cudaFuncSetAttribute(gemm_k<1>, cudaFuncAttributeMaxDynamicSharedMemorySize, GEMM_SMEM);
    cudaFuncSetAttribute(gemm_k<2>, cudaFuncAttributeMaxDynamicSharedMemorySize, GEMM_SMEM);

    const size_t OFF_WOUT = 0;
    const size_t OFF_FF1  = (size_t)8 * 512 * 256;
    const size_t OFF_FF2  = OFF_FF1 + (size_t)4 * 1024 * 256;
    const size_t OFF_VOC  = OFF_FF2 + (size_t)4 * 256 * 1024;

    const int ELT = Mrows * 64 / 256;
    const int LNB = Mrows / 8;
    const int SCB = Bb * Cn * (Dd / 64);
    const int CAB = Bb * Dd * Nn / 256;
    const int MB  = Mrows / 128;   // 256

    embed_k<<<ELT, 256>>>(batch, emb);

    for (int j = 0; j < 8; j++)
        wconv_k<<<dim3(16, 8), 256>>>(s4_Wout + (size_t)j*256*512, 256, 512,
                                      pwh + OFF_WOUT + (size_t)j*512*256,
                                      pwl + OFF_WOUT + (size_t)j*512*256);
    for (int l = 0; l < NLAY; l++)
        wconv_k<<<dim3(32, 8), 256>>>(ff_W1 + (size_t)l*256*1024, 256, 1024,
                                      pwh + OFF_FF1 + (size_t)l*1024*256,
                                      pwl + OFF_FF1 + (size_t)l*1024*256);
    for (int l = 0; l < NLAY; l++)
        wconv_k<<<dim3(8, 32), 256>>>(ff_W2 + (size_t)l*1024*256, 1024, 256,
                                      pwh + OFF_FF2 + (size_t)l*256*1024,
                                      pwl + OFF_FF2 + (size_t)l*256*1024);
    wconv_k<<<dim3(32, 8), 256>>>(W_vocab, 256, 1024, pwh + OFF_VOC, pwl + OFF_VOC);

    for (int l = 0; l < NLAY; l++) {
        for (int s = 0; s < 2; s++) {
            int j = 2 * l + s;
            s4_params_k<<<DN / 256, 256>>>(s4_log_dt + (size_t)j * Dd,
                                           s4_Alogre + (size_t)j * DN,
                                           s4_Aim    + (size_t)j * DN,
                                           s4_Cre    + (size_t)j * DN,
                                           s4_Cim    + (size_t)j * DN);
            layernorm_k<0><<<LNB, 256>>>(px, s4_ln_w + (size_t)j * Dd,
                                         s4_ln_b + (size_t)j * Dd, pu);
            scan1_k<<<SCB, 256>>>();
            carry_k<<<CAB, 256>>>();
            scan3_k<<<SCB, 256>>>(s4_Dsk + (size_t)j * Dd);
            gemm_k<0><<<dim3(2, MB), 512, GEMM_SMEM>>>(
                pah, pal, pwh + OFF_WOUT + (size_t)j*512*256, pwl + OFF_WOUT + (size_t)j*512*256,
                s4_bout + (size_t)j * 512, pz, nullptr, nullptr, 512, 256);
            glu_k<<<ELT, 256>>>();
        }
        layernorm_k<1><<<LNB, 256>>>(px, ff_ln_w + (size_t)l * Dd,
                                     ff_ln_b + (size_t)l * Dd, nullptr);
        gemm_k<1><<<dim3(4, MB), 512, GEMM_SMEM>>>(
            pah, pal, pwh + OFF_FF1 + (size_t)l*1024*256, pwl + OFF_FF1 + (size_t)l*1024*256,
            ff_b1 + (size_t)l * 1024, nullptr, pbh, pbl, 1024, 256);
        gemm_k<2><<<dim3(1, MB), 512, GEMM_SMEM>>>(
            pbh, pbl, pwh + OFF_FF2 + (size_t)l*256*1024, pwl + OFF_FF2 + (size_t)l*256*1024,
            ff_b2 + (size_t)l * 256, px, nullptr, nullptr, 256, 1024);
    }

    layernorm_k<1><<<LNB, 256>>>(px, fin_ln_w, fin_ln_b, nullptr);
    gemm_k<0><<<dim3(4, MB), 512, GEMM_SMEM>>>(
        pah, pal, pwh + OFF_VOC, pwl + OFF_VOC,
        b_vocab, (float*)d_out, nullptr, nullptr, 1024, 256);
}